// round 15
// baseline (speedup 1.0000x reference)
#include <cuda_runtime.h>
#include <cuda_fp16.h>
#include <cstdint>

#define CC     64
#define KK9    9
#define NH     5
#define NMAX   150000
#define TMM    128
#define MAXT   ((NMAX + TMM - 1) / TMM)     // 1172
#define BN_EPS 1e-5f

// ---------------- device global scratch (no allocations allowed) ----------------
__device__ __half g_f16[(size_t)NMAX * CC];                    // features (fp16)
__device__ __half g_B16[(size_t)NH * KK9 * 4096];              // weights fp16, swizzled
__device__ __half g_h16[(size_t)NH * NMAX * CC];               // 96 MB intermediate (fp16)
__device__ float g_part[(size_t)NH * 2 * CC * MAXT];           // [head][stat][chan][tile]
__device__ float g_scale[NH * CC];
__device__ float g_shift[NH * CC];

// ---------------- helpers ----------------
__device__ __forceinline__ uint32_t smem_u32(const void* p) {
    uint32_t a;
    asm("{ .reg .u64 t; cvta.to.shared.u64 t, %1; cvt.u32.u64 %0, t; }" : "=r"(a) : "l"(p));
    return a;
}
__device__ __forceinline__ void cpa16(uint32_t dst, const void* src, uint32_t sz) {
    asm volatile("cp.async.cg.shared.global [%0], [%1], 16, %2;"
                 :: "r"(dst), "l"(src), "r"(sz) : "memory");
}
__device__ __forceinline__ void cpa_commit() {
    asm volatile("cp.async.commit_group;" ::: "memory");
}
__device__ __forceinline__ void ldx4(uint32_t* r, uint32_t addr) {
    asm volatile("ldmatrix.sync.aligned.m8n8.x4.shared.b16 {%0,%1,%2,%3}, [%4];"
                 : "=r"(r[0]), "=r"(r[1]), "=r"(r[2]), "=r"(r[3]) : "r"(addr));
}
__device__ __forceinline__ void mma_f16(float* c, const uint32_t* a, const uint32_t* b) {
    asm volatile(
        "mma.sync.aligned.m16n8k16.row.col.f32.f16.f16.f32 "
        "{%0,%1,%2,%3}, {%4,%5,%6,%7}, {%8,%9}, {%0,%1,%2,%3};"
        : "+f"(c[0]), "+f"(c[1]), "+f"(c[2]), "+f"(c[3])
        : "r"(a[0]), "r"(a[1]), "r"(a[2]), "r"(a[3]), "r"(b[0]), "r"(b[1]));
}

// ---------------- prep kernel (features + weights merged) ----------------
__global__ __launch_bounds__(256) void prep_all(const float* __restrict__ f,
                                                const float* __restrict__ w, int nf) {
    int i = blockIdx.x * blockDim.x + threadIdx.x;
    if (i < nf) g_f16[i] = __float2half(f[i]);
    if (i < NH * KK9 * 4096) {
        int slab = i >> 12;
        int r = i & 4095;
        int c = r >> 6;        // K index
        int o = r & 63;        // N index
        int e = (o * 8 + ((c >> 3) ^ (o & 7))) * 8 + (c & 7);
        g_B16[(size_t)slab * 4096 + e] = __float2half(w[i]);
    }
}

// ---------------- pass1: fp16 mma.sync gather-GEMM, 3-stage / 1-sync loop ----------
// SMEM: A: 3 stages x 16KB = 48KB at 0
//       B: 3 stages x 8KB  = 24KB at 49152
//       red: 2KB at 73728            -> 74KB total, 3 CTAs/SM
#define SM_A    0u
#define SM_B    49152u
#define SM_RED  73728u
#define SM_TOT  75776u

// gather with a pre-loaded neighbor index (no LDG on the issue path)
__device__ __forceinline__ void gatherA_idx(uint32_t sb, int stage, int idx)
{
    const int t   = threadIdx.x;
    const int row = t >> 1;          // 128 rows, 2 threads each
    uint32_t sz = (idx >= 0) ? 16u : 0u;
    int ic = (idx >= 0) ? idx : 0;
    const char* src = (const char*)g_f16 + (size_t)ic * 128 + (t & 1) * 64;
    uint32_t dbase = sb + SM_A + (uint32_t)stage * 16384u + (uint32_t)row * 128u;
    #pragma unroll
    for (int j = 0; j < 4; ++j) {
        int c16 = (t & 1) * 4 + j;
        uint32_t off = (uint32_t)((c16 ^ (row & 7)) << 4);
        cpa16(dbase + off, src + j * 16, sz);
    }
}

__device__ __forceinline__ void copyB(uint32_t sb, int stage, int slab) {
    const int t = threadIdx.x;
    const char* src = (const char*)g_B16 + (size_t)slab * 8192;
    uint32_t dst = sb + SM_B + (uint32_t)stage * 8192u;
    #pragma unroll
    for (int j = 0; j < 2; ++j) {
        int i = t + j * 256;
        cpa16(dst + (uint32_t)i * 16u, src + (size_t)i * 16, 16u);
    }
}

__global__ __launch_bounds__(256, 3) void pass1_mma(
    const int* __restrict__ nbr, int Nv, int ntiles)
{
    extern __shared__ char smem[];
    const uint32_t sb = smem_u32(smem);
    const int tid  = threadIdx.x;
    const int wid  = tid >> 5;
    const int lane = tid & 31;
    const int m0   = blockIdx.x * TMM;
    const int head = blockIdx.y;

    const int wm = wid & 3;            // 4 M-warps (32 rows each)
    const int wn = wid >> 2;           // 2 N-warps (32 cols each)
    const int warpM0 = wm * 32;
    const int warpN0 = wn * 32;

    // this thread's gather row + clamped nbr row pointer
    const int m_row   = m0 + (tid >> 1);
    const bool mvalid = (m_row < Nv);
    const int* nbrrow = nbr + (size_t)(mvalid ? m_row : 0) * KK9;

    float acc[2][4][4];                // [mf][nf][4]
    #pragma unroll
    for (int i = 0; i < 2; ++i)
        #pragma unroll
        for (int j = 0; j < 4; ++j)
            #pragma unroll
            for (int q = 0; q < 4; ++q) acc[i][j][q] = 0.f;

    // prologue: idx(k=0) -> slab 0 group; prefetch idx(k=1)
    int idx0 = mvalid ? __ldg(nbrrow + 0) : -1;
    gatherA_idx(sb, 0, idx0);
    copyB(sb, 0, head * KK9 + 0);
    cpa_commit();
    int idx_nxt = mvalid ? __ldg(nbrrow + 1) : -1;   // for k=1 (latency hidden)

    // 3-stage ring, ONE barrier per slab.
    #pragma unroll 1
    for (int k = 0; k < KK9; ++k) {
        const int st = k % 3;
        if (k + 1 < KK9) {
            const int nx = (k + 1) % 3;
            gatherA_idx(sb, nx, idx_nxt);
            copyB(sb, nx, head * KK9 + k + 1);
            cpa_commit();
            if (k + 2 < KK9)
                idx_nxt = mvalid ? __ldg(nbrrow + k + 2) : -1;
            asm volatile("cp.async.wait_group 1;" ::: "memory");  // slab k resident
        } else {
            asm volatile("cp.async.wait_group 0;" ::: "memory");
        }
        __syncthreads();

        const uint32_t Ah = sb + SM_A + (uint32_t)st * 16384u;
        const uint32_t Bh = sb + SM_B + (uint32_t)st * 8192u;

        #pragma unroll
        for (int kk = 0; kk < 4; ++kk) {
            uint32_t ah[2][4];
            #pragma unroll
            for (int mf = 0; mf < 2; ++mf) {
                int rr = warpM0 + mf * 16 + (lane & 7) + ((lane >> 3) & 1) * 8;
                int c16 = kk * 2 + (lane >> 4);
                uint32_t byte = (uint32_t)(rr * 128 + ((c16 ^ (rr & 7)) << 4));
                ldx4(ah[mf], Ah + byte);
            }
            uint32_t bh[2][4];             // [pair p: nf {2p,2p+1}]
            #pragma unroll
            for (int p = 0; p < 2; ++p) {
                int nn = warpN0 + p * 16 + (lane & 7) + ((lane >> 4) << 3);
                int c16 = kk * 2 + ((lane >> 3) & 1);
                uint32_t byte = (uint32_t)(nn * 128 + ((c16 ^ (nn & 7)) << 4));
                ldx4(bh[p], Bh + byte);
            }
            #pragma unroll
            for (int mf = 0; mf < 2; ++mf)
                #pragma unroll
                for (int nf = 0; nf < 4; ++nf)
                    mma_f16(acc[mf][nf], ah[mf], &bh[nf >> 1][(nf & 1) * 2]);
        }
    }

    // ---- epilogue: write g_h16 (fp16) + BN partials ----
    __half* hb = g_h16 + (size_t)head * Nv * CC;
    #pragma unroll
    for (int mf = 0; mf < 2; ++mf)
        #pragma unroll
        for (int nf = 0; nf < 4; ++nf) {
            int r = m0 + warpM0 + mf * 16 + (lane >> 2);
            int c = warpN0 + nf * 8 + (lane & 3) * 2;
            float* a = acc[mf][nf];
            if (r < Nv)
                *(__half2*)(hb + (size_t)r * CC + c) = __floats2half2_rn(a[0], a[1]);
            if (r + 8 < Nv)
                *(__half2*)(hb + (size_t)(r + 8) * CC + c) = __floats2half2_rn(a[2], a[3]);
        }

    float* red = (float*)(smem + SM_RED);   // [4 wm][2 stat][64 col]
    #pragma unroll
    for (int nf = 0; nf < 4; ++nf) {
        float s0 = 0.f, s1 = 0.f, q0 = 0.f, q1 = 0.f;
        #pragma unroll
        for (int mf = 0; mf < 2; ++mf) {
            float* a = acc[mf][nf];
            s0 += a[0] + a[2];  q0 += a[0] * a[0] + a[2] * a[2];
            s1 += a[1] + a[3];  q1 += a[1] * a[1] + a[3] * a[3];
        }
        #pragma unroll
        for (int sh = 4; sh < 32; sh <<= 1) {
            s0 += __shfl_xor_sync(0xffffffffu, s0, sh);
            s1 += __shfl_xor_sync(0xffffffffu, s1, sh);
            q0 += __shfl_xor_sync(0xffffffffu, q0, sh);
            q1 += __shfl_xor_sync(0xffffffffu, q1, sh);
        }
        if (lane < 4) {
            int c = warpN0 + nf * 8 + lane * 2;
            red[(wm * 2 + 0) * 64 + c]     = s0;
            red[(wm * 2 + 0) * 64 + c + 1] = s1;
            red[(wm * 2 + 1) * 64 + c]     = q0;
            red[(wm * 2 + 1) * 64 + c + 1] = q1;
        }
    }
    __syncthreads();
    if (tid < 128) {
        int w = tid >> 6, col = tid & 63;
        float v = red[(0 * 2 + w) * 64 + col] + red[(1 * 2 + w) * 64 + col]
                + red[(2 * 2 + w) * 64 + col] + red[(3 * 2 + w) * 64 + col];
        g_part[((((size_t)head * 2 + w) * CC) + col) * MAXT + blockIdx.x] = v;
    }
}

// ---------------- BN stats reduce: one warp-block per (head, chan) ----------------
__global__ __launch_bounds__(32) void reduce_stats(
    const float* __restrict__ gamma, const float* __restrict__ beta,
    int Nv, int ntiles)
{
    int gw   = blockIdx.x;
    int lane = threadIdx.x;
    int head = gw / CC, c = gw % CC;
    const float* ps = g_part + (((size_t)head * 2 + 0) * CC + c) * MAXT;
    const float* pq = g_part + (((size_t)head * 2 + 1) * CC + c) * MAXT;
    float s = 0.f, q = 0.f;
    int nt4 = ntiles >> 2;
    const float4* ps4 = (const float4*)ps;
    const float4* pq4 = (const float4*)pq;
    for (int i = lane; i < nt4; i += 32) {
        float4 a = ps4[i], b = pq4[i];
        s += (a.x + a.y) + (a.z + a.w);
        q += (b.x + b.y) + (b.z + b.w);
    }
    for (int i = nt4 * 4 + lane; i < ntiles; i += 32) { s += ps[i]; q += pq[i]; }
    #pragma unroll
    for (int sh = 16; sh > 0; sh >>= 1) {
        s += __shfl_down_sync(0xffffffffu, s, sh);
        q += __shfl_down_sync(0xffffffffu, q, sh);
    }
    if (lane == 0) {
        float invN = 1.f / (float)Nv;
        float mean = s * invN;
        float var  = q * invN - mean * mean;
        float inv  = rsqrtf(var + BN_EPS);
        float sc   = inv * gamma[gw];
        g_scale[gw] = sc;
        g_shift[gw] = beta[gw] - mean * sc;
    }
}

// ---------------- pass 2: 4 voxels/warp, 8 lanes/voxel, smem-staged W1 ----------------
__global__ __launch_bounds__(256) void pass2_kernel(
    const float* __restrict__ W1_0, const float* __restrict__ b1_0,
    const float* __restrict__ W1_1, const float* __restrict__ b1_1,
    const float* __restrict__ W1_2, const float* __restrict__ b1_2,
    const float* __restrict__ W1_3, const float* __restrict__ b1_3,
    const float* __restrict__ W1_4, const float* __restrict__ b1_4,
    float* __restrict__ out, int Nv)
{
    __shared__ float sW[NH][CC][4];   // 5 KB, padded oc->4
    __shared__ float sB[NH][4];

    // cooperative fill (uniform control flow; no per-thread local arrays)
    for (int i = threadIdx.x; i < NH * CC; i += 256) {
        int hh = i >> 6, c = i & 63;
        const float* W1; const float* b1; int oc;
        switch (hh) {
            case 0:  W1 = W1_0; b1 = b1_0; oc = 3; break;
            case 1:  W1 = W1_1; b1 = b1_1; oc = 2; break;
            case 2:  W1 = W1_2; b1 = b1_2; oc = 1; break;
            case 3:  W1 = W1_3; b1 = b1_3; oc = 3; break;
            default: W1 = W1_4; b1 = b1_4; oc = 2; break;
        }
        float4 v;
        v.x = __ldg(W1 + c * oc + 0);
        v.y = (oc > 1) ? __ldg(W1 + c * oc + 1) : 0.f;
        v.z = (oc > 2) ? __ldg(W1 + c * oc + 2) : 0.f;
        v.w = 0.f;
        *(float4*)&sW[hh][c][0] = v;
        if (c < 4) sB[hh][c] = (c < oc) ? __ldg(b1 + c) : 0.f;
    }
    __syncthreads();

    const int gw   = (blockIdx.x * blockDim.x + threadIdx.x) >> 5;   // warp id
    const int lane = threadIdx.x & 31;
    const int g    = lane >> 3;          // voxel-in-warp (0..3)
    const int s    = lane & 7;           // channel octet (0..7)

    long long r = (long long)gw * 4 + g;          // global row = head*Nv + n
    if (r >= (long long)NH * Nv) return;          // after syncthreads: safe
    const int head = (int)(r / Nv);
    const int n    = (int)(r - (long long)head * Nv);

    // 8 channels per lane: one coalesced float4 (lanes cover 512B contiguous)
    const __half* hp = g_h16 + (size_t)r * CC + s * 8;
    float4 hraw = *(const float4*)hp;
    const __half2* hh2 = (const __half2*)&hraw;

    const int cb = head * CC + s * 8;
    float4 sc0 = *(const float4*)(g_scale + cb);
    float4 sc1 = *(const float4*)(g_scale + cb + 4);
    float4 sf0 = *(const float4*)(g_shift + cb);
    float4 sf1 = *(const float4*)(g_shift + cb + 4);

    float y[8];
    {
        float2 t0 = __half22float2(hh2[0]);
        float2 t1 = __half22float2(hh2[1]);
        float2 t2 = __half22float2(hh2[2]);
        float2 t3 = __half22float2(hh2[3]);
        y[0] = fmaxf(0.f, fmaf(t0.x, sc0.x, sf0.x));
        y[1] = fmaxf(0.f, fmaf(t0.y, sc0.y, sf0.y));
        y[2] = fmaxf(0.f, fmaf(t1.x, sc0.z, sf0.z));
        y[3] = fmaxf(0.f, fmaf(t1.y, sc0.w, sf0.w));
        y[4] = fmaxf(0.f, fmaf(t2.x, sc1.x, sf1.x));
        y[5] = fmaxf(0.f, fmaf(t2.y, sc1.y, sf1.y));
        y[6] = fmaxf(0.f, fmaf(t3.x, sc1.z, sf1.z));
        y[7] = fmaxf(0.f, fmaf(t3.y, sc1.w, sf1.w));
    }

    // 4 padded outputs at once: 8 contiguous smem float4 weight rows per lane
    const float4* Wp = (const float4*)&sW[head][s * 8][0];
    float4 a4 = make_float4(0.f, 0.f, 0.f, 0.f);
    #pragma unroll
    for (int j = 0; j < 8; ++j) {
        float4 w4 = Wp[j];
        a4.x = fmaf(y[j], w4.x, a4.x);
        a4.y = fmaf(y[j], w4.y, a4.y);
        a4.z = fmaf(y[j], w4.z, a4.z);
        a4.w = fmaf(y[j], w4.w, a4.w);
    }
    const uint32_t gmask = 0xFFu << (g * 8);
    #pragma unroll
    for (int sh = 4; sh > 0; sh >>= 1) {
        a4.x += __shfl_down_sync(gmask, a4.x, sh, 8);
        a4.y += __shfl_down_sync(gmask, a4.y, sh, 8);
        a4.z += __shfl_down_sync(gmask, a4.z, sh, 8);
    }
    if (s == 0) {
        int oc, off;
        switch (head) {
            case 0:  oc = 3; off = 0; break;
            case 1:  oc = 2; off = 3; break;
            case 2:  oc = 1; off = 5; break;
            case 3:  oc = 3; off = 6; break;
            default: oc = 2; off = 9; break;
        }
        size_t ob = (size_t)off * Nv + (size_t)n * oc;
        out[ob + 0] = a4.x + sB[head][0];
        if (oc > 1) out[ob + 1] = a4.y + sB[head][1];
        if (oc > 2) out[ob + 2] = a4.z + sB[head][2];
    }
}

// ---------------------------------------------------------------------------
extern "C" void kernel_launch(void* const* d_in, const int* in_sizes, int n_in,
                              void* d_out, int out_size)
{
    const float* feat  = (const float*)d_in[0];
    const int*   nbr   = (const int*)  d_in[1];
    const float* W3    = (const float*)d_in[2];
    const float* gamma = (const float*)d_in[3];
    const float* beta  = (const float*)d_in[4];

    int Nv = in_sizes[0] / CC;
    if (Nv > NMAX) Nv = NMAX;
    int ntiles = (Nv + TMM - 1) / TMM;

    cudaFuncSetAttribute(pass1_mma, cudaFuncAttributeMaxDynamicSharedMemorySize, SM_TOT);

    int nf = Nv * CC;
    prep_all<<<(nf + 255) / 256, 256>>>(feat, W3, nf);

    dim3 g1(ntiles, NH);
    pass1_mma<<<g1, 256, SM_TOT>>>(nbr, Nv, ntiles);

    reduce_stats<<<NH * CC, 32>>>(gamma, beta, Nv, ntiles);

    long long nrows   = (long long)NH * Nv;                 // 750000
    long long nwarps  = (nrows + 3) / 4;
    long long nthread = nwarps * 32;
    int blocks2 = (int)((nthread + 255) / 256);
    pass2_kernel<<<blocks2, 256>>>(
        (const float*)d_in[5],  (const float*)d_in[6],
        (const float*)d_in[7],  (const float*)d_in[8],
        (const float*)d_in[9],  (const float*)d_in[10],
        (const float*)d_in[11], (const float*)d_in[12],
        (const float*)d_in[13], (const float*)d_in[14],
        (float*)d_out, Nv);
}

// round 16
// speedup vs baseline: 1.3777x; 1.3777x over previous
#include <cuda_runtime.h>
#include <cuda_fp16.h>
#include <cstdint>

#define CC     64
#define KK9    9
#define NH     5
#define NMAX   150000
#define TMM    128
#define MAXT   ((NMAX + TMM - 1) / TMM)     // 1172
#define BN_EPS 1e-5f

// ---------------- device global scratch (no allocations allowed) ----------------
__device__ __half g_f16[(size_t)NMAX * CC];                    // features (fp16)
__device__ __half g_B16[(size_t)NH * KK9 * 4096];              // weights fp16, swizzled
__device__ __half g_h16[(size_t)NH * NMAX * CC];               // 96 MB intermediate (fp16)
__device__ float g_part[(size_t)NH * 2 * CC * MAXT];           // [head][stat][chan][tile]
__device__ float g_scale[NH * CC];
__device__ float g_shift[NH * CC];

// ---------------- helpers ----------------
__device__ __forceinline__ uint32_t smem_u32(const void* p) {
    uint32_t a;
    asm("{ .reg .u64 t; cvta.to.shared.u64 t, %1; cvt.u32.u64 %0, t; }" : "=r"(a) : "l"(p));
    return a;
}
__device__ __forceinline__ void cpa16(uint32_t dst, const void* src, uint32_t sz) {
    asm volatile("cp.async.cg.shared.global [%0], [%1], 16, %2;"
                 :: "r"(dst), "l"(src), "r"(sz) : "memory");
}
__device__ __forceinline__ void cpa_commit() {
    asm volatile("cp.async.commit_group;" ::: "memory");
}
__device__ __forceinline__ void ldx4(uint32_t* r, uint32_t addr) {
    asm volatile("ldmatrix.sync.aligned.m8n8.x4.shared.b16 {%0,%1,%2,%3}, [%4];"
                 : "=r"(r[0]), "=r"(r[1]), "=r"(r[2]), "=r"(r[3]) : "r"(addr));
}
__device__ __forceinline__ void mma_f16(float* c, const uint32_t* a, const uint32_t* b) {
    asm volatile(
        "mma.sync.aligned.m16n8k16.row.col.f32.f16.f16.f32 "
        "{%0,%1,%2,%3}, {%4,%5,%6,%7}, {%8,%9}, {%0,%1,%2,%3};"
        : "+f"(c[0]), "+f"(c[1]), "+f"(c[2]), "+f"(c[3])
        : "r"(a[0]), "r"(a[1]), "r"(a[2]), "r"(a[3]), "r"(b[0]), "r"(b[1]));
}

// ---------------- prep kernel (features + weights merged) ----------------
__global__ __launch_bounds__(256) void prep_all(const float* __restrict__ f,
                                                const float* __restrict__ w, int nf) {
    int i = blockIdx.x * blockDim.x + threadIdx.x;
    if (i < nf) g_f16[i] = __float2half(f[i]);
    if (i < NH * KK9 * 4096) {
        int slab = i >> 12;
        int r = i & 4095;
        int c = r >> 6;        // K index
        int o = r & 63;        // N index
        int e = (o * 8 + ((c >> 3) ^ (o & 7))) * 8 + (c & 7);
        g_B16[(size_t)slab * 4096 + e] = __float2half(w[i]);
    }
}

// ---------------- pass1: fp16 mma.sync gather-GEMM, 3-stage / 1-sync loop ----------
// SMEM: A: 3 stages x 16KB = 48KB at 0
//       B: 3 stages x 8KB  = 24KB at 49152
//       red: 2KB at 73728            -> 74KB total, 3 CTAs/SM
#define SM_A    0u
#define SM_B    49152u
#define SM_RED  73728u
#define SM_TOT  75776u

// gather with a pre-loaded neighbor index (no LDG on the issue path)
__device__ __forceinline__ void gatherA_idx(uint32_t sb, int stage, int idx)
{
    const int t   = threadIdx.x;
    const int row = t >> 1;          // 128 rows, 2 threads each
    uint32_t sz = (idx >= 0) ? 16u : 0u;
    int ic = (idx >= 0) ? idx : 0;
    const char* src = (const char*)g_f16 + (size_t)ic * 128 + (t & 1) * 64;
    uint32_t dbase = sb + SM_A + (uint32_t)stage * 16384u + (uint32_t)row * 128u;
    #pragma unroll
    for (int j = 0; j < 4; ++j) {
        int c16 = (t & 1) * 4 + j;
        uint32_t off = (uint32_t)((c16 ^ (row & 7)) << 4);
        cpa16(dbase + off, src + j * 16, sz);
    }
}

__device__ __forceinline__ void copyB(uint32_t sb, int stage, int slab) {
    const int t = threadIdx.x;
    const char* src = (const char*)g_B16 + (size_t)slab * 8192;
    uint32_t dst = sb + SM_B + (uint32_t)stage * 8192u;
    #pragma unroll
    for (int j = 0; j < 2; ++j) {
        int i = t + j * 256;
        cpa16(dst + (uint32_t)i * 16u, src + (size_t)i * 16, 16u);
    }
}

__global__ __launch_bounds__(256, 3) void pass1_mma(
    const int* __restrict__ nbr, int Nv, int ntiles)
{
    extern __shared__ char smem[];
    const uint32_t sb = smem_u32(smem);
    const int tid  = threadIdx.x;
    const int wid  = tid >> 5;
    const int lane = tid & 31;
    const int m0   = blockIdx.x * TMM;
    const int head = blockIdx.y;

    const int wm = wid & 3;            // 4 M-warps (32 rows each)
    const int wn = wid >> 2;           // 2 N-warps (32 cols each)
    const int warpM0 = wm * 32;
    const int warpN0 = wn * 32;

    // this thread's gather row + clamped nbr row pointer
    const int m_row   = m0 + (tid >> 1);
    const bool mvalid = (m_row < Nv);
    const int* nbrrow = nbr + (size_t)(mvalid ? m_row : 0) * KK9;

    float acc[2][4][4];                // [mf][nf][4]
    #pragma unroll
    for (int i = 0; i < 2; ++i)
        #pragma unroll
        for (int j = 0; j < 4; ++j)
            #pragma unroll
            for (int q = 0; q < 4; ++q) acc[i][j][q] = 0.f;

    // prologue: idx(k=0) -> slab 0 group; prefetch idx(k=1)
    int idx0 = mvalid ? __ldg(nbrrow + 0) : -1;
    gatherA_idx(sb, 0, idx0);
    copyB(sb, 0, head * KK9 + 0);
    cpa_commit();
    int idx_nxt = mvalid ? __ldg(nbrrow + 1) : -1;   // for k=1 (latency hidden)

    // 3-stage ring, ONE barrier per slab.
    #pragma unroll 1
    for (int k = 0; k < KK9; ++k) {
        const int st = k % 3;
        if (k + 1 < KK9) {
            const int nx = (k + 1) % 3;
            gatherA_idx(sb, nx, idx_nxt);
            copyB(sb, nx, head * KK9 + k + 1);
            cpa_commit();
            if (k + 2 < KK9)
                idx_nxt = mvalid ? __ldg(nbrrow + k + 2) : -1;
            asm volatile("cp.async.wait_group 1;" ::: "memory");  // slab k resident
        } else {
            asm volatile("cp.async.wait_group 0;" ::: "memory");
        }
        __syncthreads();

        const uint32_t Ah = sb + SM_A + (uint32_t)st * 16384u;
        const uint32_t Bh = sb + SM_B + (uint32_t)st * 8192u;

        #pragma unroll
        for (int kk = 0; kk < 4; ++kk) {
            uint32_t ah[2][4];
            #pragma unroll
            for (int mf = 0; mf < 2; ++mf) {
                int rr = warpM0 + mf * 16 + (lane & 7) + ((lane >> 3) & 1) * 8;
                int c16 = kk * 2 + (lane >> 4);
                uint32_t byte = (uint32_t)(rr * 128 + ((c16 ^ (rr & 7)) << 4));
                ldx4(ah[mf], Ah + byte);
            }
            uint32_t bh[2][4];             // [pair p: nf {2p,2p+1}]
            #pragma unroll
            for (int p = 0; p < 2; ++p) {
                int nn = warpN0 + p * 16 + (lane & 7) + ((lane >> 4) << 3);
                int c16 = kk * 2 + ((lane >> 3) & 1);
                uint32_t byte = (uint32_t)(nn * 128 + ((c16 ^ (nn & 7)) << 4));
                ldx4(bh[p], Bh + byte);
            }
            #pragma unroll
            for (int mf = 0; mf < 2; ++mf)
                #pragma unroll
                for (int nf = 0; nf < 4; ++nf)
                    mma_f16(acc[mf][nf], ah[mf], &bh[nf >> 1][(nf & 1) * 2]);
        }
    }

    // ---- epilogue: write g_h16 (fp16) + BN partials ----
    __half* hb = g_h16 + (size_t)head * Nv * CC;
    #pragma unroll
    for (int mf = 0; mf < 2; ++mf)
        #pragma unroll
        for (int nf = 0; nf < 4; ++nf) {
            int r = m0 + warpM0 + mf * 16 + (lane >> 2);
            int c = warpN0 + nf * 8 + (lane & 3) * 2;
            float* a = acc[mf][nf];
            if (r < Nv)
                *(__half2*)(hb + (size_t)r * CC + c) = __floats2half2_rn(a[0], a[1]);
            if (r + 8 < Nv)
                *(__half2*)(hb + (size_t)(r + 8) * CC + c) = __floats2half2_rn(a[2], a[3]);
        }

    float* red = (float*)(smem + SM_RED);   // [4 wm][2 stat][64 col]
    #pragma unroll
    for (int nf = 0; nf < 4; ++nf) {
        float s0 = 0.f, s1 = 0.f, q0 = 0.f, q1 = 0.f;
        #pragma unroll
        for (int mf = 0; mf < 2; ++mf) {
            float* a = acc[mf][nf];
            s0 += a[0] + a[2];  q0 += a[0] * a[0] + a[2] * a[2];
            s1 += a[1] + a[3];  q1 += a[1] * a[1] + a[3] * a[3];
        }
        #pragma unroll
        for (int sh = 4; sh < 32; sh <<= 1) {
            s0 += __shfl_xor_sync(0xffffffffu, s0, sh);
            s1 += __shfl_xor_sync(0xffffffffu, s1, sh);
            q0 += __shfl_xor_sync(0xffffffffu, q0, sh);
            q1 += __shfl_xor_sync(0xffffffffu, q1, sh);
        }
        if (lane < 4) {
            int c = warpN0 + nf * 8 + lane * 2;
            red[(wm * 2 + 0) * 64 + c]     = s0;
            red[(wm * 2 + 0) * 64 + c + 1] = s1;
            red[(wm * 2 + 1) * 64 + c]     = q0;
            red[(wm * 2 + 1) * 64 + c + 1] = q1;
        }
    }
    __syncthreads();
    if (tid < 128) {
        int w = tid >> 6, col = tid & 63;
        float v = red[(0 * 2 + w) * 64 + col] + red[(1 * 2 + w) * 64 + col]
                + red[(2 * 2 + w) * 64 + col] + red[(3 * 2 + w) * 64 + col];
        g_part[((((size_t)head * 2 + w) * CC) + col) * MAXT + blockIdx.x] = v;
    }
}

// ---------------- BN stats reduce: one warp-block per (head, chan) ----------------
__global__ __launch_bounds__(32) void reduce_stats(
    const float* __restrict__ gamma, const float* __restrict__ beta,
    int Nv, int ntiles)
{
    int gw   = blockIdx.x;
    int lane = threadIdx.x;
    int head = gw / CC, c = gw % CC;
    const float* ps = g_part + (((size_t)head * 2 + 0) * CC + c) * MAXT;
    const float* pq = g_part + (((size_t)head * 2 + 1) * CC + c) * MAXT;
    float s = 0.f, q = 0.f;
    int nt4 = ntiles >> 2;
    const float4* ps4 = (const float4*)ps;
    const float4* pq4 = (const float4*)pq;
    for (int i = lane; i < nt4; i += 32) {
        float4 a = ps4[i], b = pq4[i];
        s += (a.x + a.y) + (a.z + a.w);
        q += (b.x + b.y) + (b.z + b.w);
    }
    for (int i = nt4 * 4 + lane; i < ntiles; i += 32) { s += ps[i]; q += pq[i]; }
    #pragma unroll
    for (int sh = 16; sh > 0; sh >>= 1) {
        s += __shfl_down_sync(0xffffffffu, s, sh);
        q += __shfl_down_sync(0xffffffffu, q, sh);
    }
    if (lane == 0) {
        float invN = 1.f / (float)Nv;
        float mean = s * invN;
        float var  = q * invN - mean * mean;
        float inv  = rsqrtf(var + BN_EPS);
        float sc   = inv * gamma[gw];
        g_scale[gw] = sc;
        g_shift[gw] = beta[gw] - mean * sc;
    }
}

// ---------------- pass 2: persistent per-head, 4 voxels/warp, 8 lanes/voxel ------
// grid (40, NH): head is block-uniform. W / scale / shift / bias hoisted into
// registers once per warp; loop over ~117 voxel-quads amortizes them.
__global__ __launch_bounds__(256) void pass2_kernel(
    const float* __restrict__ W1_0, const float* __restrict__ b1_0,
    const float* __restrict__ W1_1, const float* __restrict__ b1_1,
    const float* __restrict__ W1_2, const float* __restrict__ b1_2,
    const float* __restrict__ W1_3, const float* __restrict__ b1_3,
    const float* __restrict__ W1_4, const float* __restrict__ b1_4,
    float* __restrict__ out, int Nv)
{
    const int head = blockIdx.y;                 // uniform over block
    const int wid  = threadIdx.x >> 5;
    const int lane = threadIdx.x & 31;
    const int g    = lane >> 3;                  // voxel-in-warp (0..3)
    const int s    = lane & 7;                   // channel octet (0..7)

    const float* W1; const float* b1; int oc; int off;
    switch (head) {
        case 0:  W1 = W1_0; b1 = b1_0; oc = 3; off = 0; break;
        case 1:  W1 = W1_1; b1 = b1_1; oc = 2; off = 3; break;
        case 2:  W1 = W1_2; b1 = b1_2; oc = 1; off = 5; break;
        case 3:  W1 = W1_3; b1 = b1_3; oc = 3; off = 6; break;
        default: W1 = W1_4; b1 = b1_4; oc = 2; off = 9; break;
    }

    // hoist weights (R12's L1-friendly 12B-stride scalar pattern, done ONCE)
    float wv[3][8];
    const float* Wrow = W1 + (size_t)(s * 8) * oc;
    #pragma unroll
    for (int o = 0; o < 3; ++o)
        #pragma unroll
        for (int j = 0; j < 8; ++j)
            wv[o][j] = (o < oc) ? __ldg(Wrow + j * oc + o) : 0.f;
    float bias[3];
    #pragma unroll
    for (int o = 0; o < 3; ++o) bias[o] = (o < oc) ? __ldg(b1 + o) : 0.f;

    // hoist BN scale/shift for this (head, octet)
    const int cb = head * CC + s * 8;
    float4 sc0 = *(const float4*)(g_scale + cb);
    float4 sc1 = *(const float4*)(g_scale + cb + 4);
    float4 sf0 = *(const float4*)(g_shift + cb);
    float4 sf1 = *(const float4*)(g_shift + cb + 4);

    const uint32_t gmask = 0xFFu << (g * 8);
    const int nq      = (Nv + 3) >> 2;                    // quads in this head
    const int wstride = gridDim.x * 8;                    // warps per head
    const __half* hbase = g_h16 + (size_t)head * Nv * CC;
    float* obase = out + (size_t)off * Nv;

    #pragma unroll 1
    for (int q = blockIdx.x * 8 + wid; q < nq; q += wstride) {
        const int n = q * 4 + g;
        const bool nv = (n < Nv);

        float4 hraw = make_float4(0.f, 0.f, 0.f, 0.f);
        if (nv) hraw = *(const float4*)(hbase + (size_t)n * CC + s * 8);
        const __half2* hh = (const __half2*)&hraw;

        float y[8];
        {
            float2 t0 = __half22float2(hh[0]);
            float2 t1 = __half22float2(hh[1]);
            float2 t2 = __half22float2(hh[2]);
            float2 t3 = __half22float2(hh[3]);
            y[0] = fmaxf(0.f, fmaf(t0.x, sc0.x, sf0.x));
            y[1] = fmaxf(0.f, fmaf(t0.y, sc0.y, sf0.y));
            y[2] = fmaxf(0.f, fmaf(t1.x, sc0.z, sf0.z));
            y[3] = fmaxf(0.f, fmaf(t1.y, sc0.w, sf0.w));
            y[4] = fmaxf(0.f, fmaf(t2.x, sc1.x, sf1.x));
            y[5] = fmaxf(0.f, fmaf(t2.y, sc1.y, sf1.y));
            y[6] = fmaxf(0.f, fmaf(t3.x, sc1.z, sf1.z));
            y[7] = fmaxf(0.f, fmaf(t3.y, sc1.w, sf1.w));
        }

        float p0 = 0.f, p1 = 0.f, p2 = 0.f;
        #pragma unroll
        for (int j = 0; j < 8; ++j) {
            p0 = fmaf(y[j], wv[0][j], p0);
            p1 = fmaf(y[j], wv[1][j], p1);
            p2 = fmaf(y[j], wv[2][j], p2);
        }
        #pragma unroll
        for (int sh = 4; sh > 0; sh >>= 1) {
            p0 += __shfl_down_sync(gmask, p0, sh, 8);
            p1 += __shfl_down_sync(gmask, p1, sh, 8);
            p2 += __shfl_down_sync(gmask, p2, sh, 8);
        }
        if (s == 0 && nv) {
            float* op = obase + (size_t)n * oc;
            op[0] = p0 + bias[0];
            if (oc > 1) op[1] = p1 + bias[1];
            if (oc > 2) op[2] = p2 + bias[2];
        }
    }
}

// ---------------------------------------------------------------------------
extern "C" void kernel_launch(void* const* d_in, const int* in_sizes, int n_in,
                              void* d_out, int out_size)
{
    const float* feat  = (const float*)d_in[0];
    const int*   nbr   = (const int*)  d_in[1];
    const float* W3    = (const float*)d_in[2];
    const float* gamma = (const float*)d_in[3];
    const float* beta  = (const float*)d_in[4];

    int Nv = in_sizes[0] / CC;
    if (Nv > NMAX) Nv = NMAX;
    int ntiles = (Nv + TMM - 1) / TMM;

    cudaFuncSetAttribute(pass1_mma, cudaFuncAttributeMaxDynamicSharedMemorySize, SM_TOT);

    int nf = Nv * CC;
    prep_all<<<(nf + 255) / 256, 256>>>(feat, W3, nf);

    dim3 g1(ntiles, NH);
    pass1_mma<<<g1, 256, SM_TOT>>>(nbr, Nv, ntiles);

    reduce_stats<<<NH * CC, 32>>>(gamma, beta, Nv, ntiles);

    dim3 g2(40, NH);
    pass2_kernel<<<g2, 256>>>(
        (const float*)d_in[5],  (const float*)d_in[6],
        (const float*)d_in[7],  (const float*)d_in[8],
        (const float*)d_in[9],  (const float*)d_in[10],
        (const float*)d_in[11], (const float*)d_in[12],
        (const float*)d_in[13], (const float*)d_in[14],
        (float*)d_out, Nv);
}

// round 17
// speedup vs baseline: 1.6466x; 1.1951x over previous
#include <cuda_runtime.h>
#include <cuda_fp16.h>
#include <cstdint>

#define CC     64
#define KK9    9
#define NH     5
#define NMAX   150000
#define TMM    128
#define MAXT   ((NMAX + TMM - 1) / TMM)     // 1172
#define BN_EPS 1e-5f

// ---------------- device global scratch (no allocations allowed) ----------------
__device__ __half g_f16[(size_t)NMAX * CC];                    // features (fp16)
__device__ __half g_B16[(size_t)NH * KK9 * 4096];              // weights fp16, swizzled
__device__ __half g_h16[(size_t)NH * NMAX * CC];               // 96 MB intermediate (fp16)
__device__ float g_part[(size_t)NH * 2 * CC * MAXT];           // [head][stat][chan][tile]
__device__ float g_scale[NH * CC];
__device__ float g_shift[NH * CC];

// ---------------- helpers ----------------
__device__ __forceinline__ uint32_t smem_u32(const void* p) {
    uint32_t a;
    asm("{ .reg .u64 t; cvta.to.shared.u64 t, %1; cvt.u32.u64 %0, t; }" : "=r"(a) : "l"(p));
    return a;
}
__device__ __forceinline__ void cpa16(uint32_t dst, const void* src, uint32_t sz) {
    asm volatile("cp.async.cg.shared.global [%0], [%1], 16, %2;"
                 :: "r"(dst), "l"(src), "r"(sz) : "memory");
}
__device__ __forceinline__ void cpa_commit() {
    asm volatile("cp.async.commit_group;" ::: "memory");
}
__device__ __forceinline__ void ldx4(uint32_t* r, uint32_t addr) {
    asm volatile("ldmatrix.sync.aligned.m8n8.x4.shared.b16 {%0,%1,%2,%3}, [%4];"
                 : "=r"(r[0]), "=r"(r[1]), "=r"(r[2]), "=r"(r[3]) : "r"(addr));
}
__device__ __forceinline__ void mma_f16(float* c, const uint32_t* a, const uint32_t* b) {
    asm volatile(
        "mma.sync.aligned.m16n8k16.row.col.f32.f16.f16.f32 "
        "{%0,%1,%2,%3}, {%4,%5,%6,%7}, {%8,%9}, {%0,%1,%2,%3};"
        : "+f"(c[0]), "+f"(c[1]), "+f"(c[2]), "+f"(c[3])
        : "r"(a[0]), "r"(a[1]), "r"(a[2]), "r"(a[3]), "r"(b[0]), "r"(b[1]));
}

// ---------------- prep kernel (features + weights merged) ----------------
__global__ __launch_bounds__(256) void prep_all(const float* __restrict__ f,
                                                const float* __restrict__ w, int nf) {
    int i = blockIdx.x * blockDim.x + threadIdx.x;
    if (i < nf) g_f16[i] = __float2half(f[i]);
    if (i < NH * KK9 * 4096) {
        int slab = i >> 12;
        int r = i & 4095;
        int c = r >> 6;        // K index
        int o = r & 63;        // N index
        int e = (o * 8 + ((c >> 3) ^ (o & 7))) * 8 + (c & 7);
        g_B16[(size_t)slab * 4096 + e] = __float2half(w[i]);
    }
}

// ---------------- pass1: fp16 mma.sync gather-GEMM, 3-stage / 1-sync loop ----------
// SMEM: A: 3 stages x 16KB = 48KB at 0
//       B: 3 stages x 8KB  = 24KB at 49152
//       red: 2KB at 73728            -> 74KB total, 3 CTAs/SM
#define SM_A    0u
#define SM_B    49152u
#define SM_RED  73728u
#define SM_TOT  75776u

// gather with a pre-loaded neighbor index (no LDG on the issue path)
__device__ __forceinline__ void gatherA_idx(uint32_t sb, int stage, int idx)
{
    const int t   = threadIdx.x;
    const int row = t >> 1;          // 128 rows, 2 threads each
    uint32_t sz = (idx >= 0) ? 16u : 0u;
    int ic = (idx >= 0) ? idx : 0;
    const char* src = (const char*)g_f16 + (size_t)ic * 128 + (t & 1) * 64;
    uint32_t dbase = sb + SM_A + (uint32_t)stage * 16384u + (uint32_t)row * 128u;
    #pragma unroll
    for (int j = 0; j < 4; ++j) {
        int c16 = (t & 1) * 4 + j;
        uint32_t off = (uint32_t)((c16 ^ (row & 7)) << 4);
        cpa16(dbase + off, src + j * 16, sz);
    }
}

__device__ __forceinline__ void copyB(uint32_t sb, int stage, int slab) {
    const int t = threadIdx.x;
    const char* src = (const char*)g_B16 + (size_t)slab * 8192;
    uint32_t dst = sb + SM_B + (uint32_t)stage * 8192u;
    #pragma unroll
    for (int j = 0; j < 2; ++j) {
        int i = t + j * 256;
        cpa16(dst + (uint32_t)i * 16u, src + (size_t)i * 16, 16u);
    }
}

__global__ __launch_bounds__(256, 3) void pass1_mma(
    const int* __restrict__ nbr, int Nv, int ntiles)
{
    extern __shared__ char smem[];
    const uint32_t sb = smem_u32(smem);
    const int tid  = threadIdx.x;
    const int wid  = tid >> 5;
    const int lane = tid & 31;
    const int m0   = blockIdx.x * TMM;
    const int head = blockIdx.y;

    const int wm = wid & 3;            // 4 M-warps (32 rows each)
    const int wn = wid >> 2;           // 2 N-warps (32 cols each)
    const int warpM0 = wm * 32;
    const int warpN0 = wn * 32;

    // this thread's gather row + clamped nbr row pointer
    const int m_row   = m0 + (tid >> 1);
    const bool mvalid = (m_row < Nv);
    const int* nbrrow = nbr + (size_t)(mvalid ? m_row : 0) * KK9;

    float acc[2][4][4];                // [mf][nf][4]
    #pragma unroll
    for (int i = 0; i < 2; ++i)
        #pragma unroll
        for (int j = 0; j < 4; ++j)
            #pragma unroll
            for (int q = 0; q < 4; ++q) acc[i][j][q] = 0.f;

    // prologue: idx(k=0) -> slab 0 group; prefetch idx(k=1)
    int idx0 = mvalid ? __ldg(nbrrow + 0) : -1;
    gatherA_idx(sb, 0, idx0);
    copyB(sb, 0, head * KK9 + 0);
    cpa_commit();
    int idx_nxt = mvalid ? __ldg(nbrrow + 1) : -1;   // for k=1 (latency hidden)

    // 3-stage ring, ONE barrier per slab.
    #pragma unroll 1
    for (int k = 0; k < KK9; ++k) {
        const int st = k % 3;
        if (k + 1 < KK9) {
            const int nx = (k + 1) % 3;
            gatherA_idx(sb, nx, idx_nxt);
            copyB(sb, nx, head * KK9 + k + 1);
            cpa_commit();
            if (k + 2 < KK9)
                idx_nxt = mvalid ? __ldg(nbrrow + k + 2) : -1;
            asm volatile("cp.async.wait_group 1;" ::: "memory");  // slab k resident
        } else {
            asm volatile("cp.async.wait_group 0;" ::: "memory");
        }
        __syncthreads();

        const uint32_t Ah = sb + SM_A + (uint32_t)st * 16384u;
        const uint32_t Bh = sb + SM_B + (uint32_t)st * 8192u;

        #pragma unroll
        for (int kk = 0; kk < 4; ++kk) {
            uint32_t ah[2][4];
            #pragma unroll
            for (int mf = 0; mf < 2; ++mf) {
                int rr = warpM0 + mf * 16 + (lane & 7) + ((lane >> 3) & 1) * 8;
                int c16 = kk * 2 + (lane >> 4);
                uint32_t byte = (uint32_t)(rr * 128 + ((c16 ^ (rr & 7)) << 4));
                ldx4(ah[mf], Ah + byte);
            }
            uint32_t bh[2][4];             // [pair p: nf {2p,2p+1}]
            #pragma unroll
            for (int p = 0; p < 2; ++p) {
                int nn = warpN0 + p * 16 + (lane & 7) + ((lane >> 4) << 3);
                int c16 = kk * 2 + ((lane >> 3) & 1);
                uint32_t byte = (uint32_t)(nn * 128 + ((c16 ^ (nn & 7)) << 4));
                ldx4(bh[p], Bh + byte);
            }
            #pragma unroll
            for (int mf = 0; mf < 2; ++mf)
                #pragma unroll
                for (int nf = 0; nf < 4; ++nf)
                    mma_f16(acc[mf][nf], ah[mf], &bh[nf >> 1][(nf & 1) * 2]);
        }
    }

    // ---- epilogue: write g_h16 (fp16) + BN partials ----
    __half* hb = g_h16 + (size_t)head * Nv * CC;
    #pragma unroll
    for (int mf = 0; mf < 2; ++mf)
        #pragma unroll
        for (int nf = 0; nf < 4; ++nf) {
            int r = m0 + warpM0 + mf * 16 + (lane >> 2);
            int c = warpN0 + nf * 8 + (lane & 3) * 2;
            float* a = acc[mf][nf];
            if (r < Nv)
                *(__half2*)(hb + (size_t)r * CC + c) = __floats2half2_rn(a[0], a[1]);
            if (r + 8 < Nv)
                *(__half2*)(hb + (size_t)(r + 8) * CC + c) = __floats2half2_rn(a[2], a[3]);
        }

    float* red = (float*)(smem + SM_RED);   // [4 wm][2 stat][64 col]
    #pragma unroll
    for (int nf = 0; nf < 4; ++nf) {
        float s0 = 0.f, s1 = 0.f, q0 = 0.f, q1 = 0.f;
        #pragma unroll
        for (int mf = 0; mf < 2; ++mf) {
            float* a = acc[mf][nf];
            s0 += a[0] + a[2];  q0 += a[0] * a[0] + a[2] * a[2];
            s1 += a[1] + a[3];  q1 += a[1] * a[1] + a[3] * a[3];
        }
        #pragma unroll
        for (int sh = 4; sh < 32; sh <<= 1) {
            s0 += __shfl_xor_sync(0xffffffffu, s0, sh);
            s1 += __shfl_xor_sync(0xffffffffu, s1, sh);
            q0 += __shfl_xor_sync(0xffffffffu, q0, sh);
            q1 += __shfl_xor_sync(0xffffffffu, q1, sh);
        }
        if (lane < 4) {
            int c = warpN0 + nf * 8 + lane * 2;
            red[(wm * 2 + 0) * 64 + c]     = s0;
            red[(wm * 2 + 0) * 64 + c + 1] = s1;
            red[(wm * 2 + 1) * 64 + c]     = q0;
            red[(wm * 2 + 1) * 64 + c + 1] = q1;
        }
    }
    __syncthreads();
    if (tid < 128) {
        int w = tid >> 6, col = tid & 63;
        float v = red[(0 * 2 + w) * 64 + col] + red[(1 * 2 + w) * 64 + col]
                + red[(2 * 2 + w) * 64 + col] + red[(3 * 2 + w) * 64 + col];
        g_part[((((size_t)head * 2 + w) * CC) + col) * MAXT + blockIdx.x] = v;
    }
}

// ---------------- BN stats reduce: one warp-block per (head, chan) ----------------
__global__ __launch_bounds__(32) void reduce_stats(
    const float* __restrict__ gamma, const float* __restrict__ beta,
    int Nv, int ntiles)
{
    int gw   = blockIdx.x;
    int lane = threadIdx.x;
    int head = gw / CC, c = gw % CC;
    const float* ps = g_part + (((size_t)head * 2 + 0) * CC + c) * MAXT;
    const float* pq = g_part + (((size_t)head * 2 + 1) * CC + c) * MAXT;
    float s = 0.f, q = 0.f;
    int nt4 = ntiles >> 2;
    const float4* ps4 = (const float4*)ps;
    const float4* pq4 = (const float4*)pq;
    for (int i = lane; i < nt4; i += 32) {
        float4 a = ps4[i], b = pq4[i];
        s += (a.x + a.y) + (a.z + a.w);
        q += (b.x + b.y) + (b.z + b.w);
    }
    for (int i = nt4 * 4 + lane; i < ntiles; i += 32) { s += ps[i]; q += pq[i]; }
    #pragma unroll
    for (int sh = 16; sh > 0; sh >>= 1) {
        s += __shfl_down_sync(0xffffffffu, s, sh);
        q += __shfl_down_sync(0xffffffffu, q, sh);
    }
    if (lane == 0) {
        float invN = 1.f / (float)Nv;
        float mean = s * invN;
        float var  = q * invN - mean * mean;
        float inv  = rsqrtf(var + BN_EPS);
        float sc   = inv * gamma[gw];
        g_scale[gw] = sc;
        g_shift[gw] = beta[gw] - mean * sc;
    }
}

// ---------------- pass 2: persistent per-head, 4 voxels/warp, 8 lanes/voxel ------
// grid (240, NH): ~8 CTAs/SM. W / scale / shift / bias hoisted into registers
// once per warp; each warp loops ~20 voxel-quads.
__global__ __launch_bounds__(256) void pass2_kernel(
    const float* __restrict__ W1_0, const float* __restrict__ b1_0,
    const float* __restrict__ W1_1, const float* __restrict__ b1_1,
    const float* __restrict__ W1_2, const float* __restrict__ b1_2,
    const float* __restrict__ W1_3, const float* __restrict__ b1_3,
    const float* __restrict__ W1_4, const float* __restrict__ b1_4,
    float* __restrict__ out, int Nv)
{
    const int head = blockIdx.y;                 // uniform over block
    const int wid  = threadIdx.x >> 5;
    const int lane = threadIdx.x & 31;
    const int g    = lane >> 3;                  // voxel-in-warp (0..3)
    const int s    = lane & 7;                   // channel octet (0..7)

    const float* W1; const float* b1; int oc; int off;
    switch (head) {
        case 0:  W1 = W1_0; b1 = b1_0; oc = 3; off = 0; break;
        case 1:  W1 = W1_1; b1 = b1_1; oc = 2; off = 3; break;
        case 2:  W1 = W1_2; b1 = b1_2; oc = 1; off = 5; break;
        case 3:  W1 = W1_3; b1 = b1_3; oc = 3; off = 6; break;
        default: W1 = W1_4; b1 = b1_4; oc = 2; off = 9; break;
    }

    // hoist weights (L1-friendly 12B-stride scalar pattern, done ONCE)
    float wv[3][8];
    const float* Wrow = W1 + (size_t)(s * 8) * oc;
    #pragma unroll
    for (int o = 0; o < 3; ++o)
        #pragma unroll
        for (int j = 0; j < 8; ++j)
            wv[o][j] = (o < oc) ? __ldg(Wrow + j * oc + o) : 0.f;
    float bias[3];
    #pragma unroll
    for (int o = 0; o < 3; ++o) bias[o] = (o < oc) ? __ldg(b1 + o) : 0.f;

    // hoist BN scale/shift for this (head, octet)
    const int cb = head * CC + s * 8;
    float4 sc0 = *(const float4*)(g_scale + cb);
    float4 sc1 = *(const float4*)(g_scale + cb + 4);
    float4 sf0 = *(const float4*)(g_shift + cb);
    float4 sf1 = *(const float4*)(g_shift + cb + 4);

    const uint32_t gmask = 0xFFu << (g * 8);
    const int nq      = (Nv + 3) >> 2;                    // quads in this head
    const int wstride = gridDim.x * 8;                    // warps per head
    const __half* hbase = g_h16 + (size_t)head * Nv * CC;
    float* obase = out + (size_t)off * Nv;

    #pragma unroll 1
    for (int q = blockIdx.x * 8 + wid; q < nq; q += wstride) {
        const int n = q * 4 + g;
        const bool nv = (n < Nv);

        float4 hraw = make_float4(0.f, 0.f, 0.f, 0.f);
        if (nv) hraw = *(const float4*)(hbase + (size_t)n * CC + s * 8);
        const __half2* hh = (const __half2*)&hraw;

        float y[8];
        {
            float2 t0 = __half22float2(hh[0]);
            float2 t1 = __half22float2(hh[1]);
            float2 t2 = __half22float2(hh[2]);
            float2 t3 = __half22float2(hh[3]);
            y[0] = fmaxf(0.f, fmaf(t0.x, sc0.x, sf0.x));
            y[1] = fmaxf(0.f, fmaf(t0.y, sc0.y, sf0.y));
            y[2] = fmaxf(0.f, fmaf(t1.x, sc0.z, sf0.z));
            y[3] = fmaxf(0.f, fmaf(t1.y, sc0.w, sf0.w));
            y[4] = fmaxf(0.f, fmaf(t2.x, sc1.x, sf1.x));
            y[5] = fmaxf(0.f, fmaf(t2.y, sc1.y, sf1.y));
            y[6] = fmaxf(0.f, fmaf(t3.x, sc1.z, sf1.z));
            y[7] = fmaxf(0.f, fmaf(t3.y, sc1.w, sf1.w));
        }

        float p0 = 0.f, p1 = 0.f, p2 = 0.f;
        #pragma unroll
        for (int j = 0; j < 8; ++j) {
            p0 = fmaf(y[j], wv[0][j], p0);
            p1 = fmaf(y[j], wv[1][j], p1);
            p2 = fmaf(y[j], wv[2][j], p2);
        }
        #pragma unroll
        for (int sh = 4; sh > 0; sh >>= 1) {
            p0 += __shfl_down_sync(gmask, p0, sh, 8);
            p1 += __shfl_down_sync(gmask, p1, sh, 8);
            p2 += __shfl_down_sync(gmask, p2, sh, 8);
        }
        if (s == 0 && nv) {
            float* op = obase + (size_t)n * oc;
            op[0] = p0 + bias[0];
            if (oc > 1) op[1] = p1 + bias[1];
            if (oc > 2) op[2] = p2 + bias[2];
        }
    }
}

// ---------------------------------------------------------------------------
extern "C" void kernel_launch(void* const* d_in, const int* in_sizes, int n_in,
                              void* d_out, int out_size)
{
    const float* feat  = (const float*)d_in[0];
    const int*   nbr   = (const int*)  d_in[1];
    const float* W3    = (const float*)d_in[2];
    const float* gamma = (const float*)d_in[3];
    const float* beta  = (const float*)d_in[4];

    int Nv = in_sizes[0] / CC;
    if (Nv > NMAX) Nv = NMAX;
    int ntiles = (Nv + TMM - 1) / TMM;

    cudaFuncSetAttribute(pass1_mma, cudaFuncAttributeMaxDynamicSharedMemorySize, SM_TOT);

    int nf = Nv * CC;
    prep_all<<<(nf + 255) / 256, 256>>>(feat, W3, nf);

    dim3 g1(ntiles, NH);
    pass1_mma<<<g1, 256, SM_TOT>>>(nbr, Nv, ntiles);

    reduce_stats<<<NH * CC, 32>>>(gamma, beta, Nv, ntiles);

    dim3 g2(240, NH);
    pass2_kernel<<<g2, 256>>>(
        (const float*)d_in[5],  (const float*)d_in[6],
        (const float*)d_in[7],  (const float*)d_in[8],
        (const float*)d_in[9],  (const float*)d_in[10],
        (const float*)d_in[11], (const float*)d_in[12],
        (const float*)d_in[13], (const float*)d_in[14],
        (float*)d_out, Nv);
}